// round 11
// baseline (speedup 1.0000x reference)
#include <cuda_runtime.h>

// FlowNetC correlation, specialized: B=4, C=128, H=W=96, PAD=20, K=1, MD=20, S1=1, S2=2
// out[b, iy*21+ix, y, x] = (1/128) * sum_c in1[b,c,y,x] * in2[b,c,y+dy,x+dx]
//
// R10: 4 output columns per thread (halves compute LDS vs 2-wide), cg over 8
// lanes (granules cg, cg+8 per 64-ch chunk), 2-pass chunk staging like R7/R9.
// The 84-accumulator problem is solved by j-halves with raw partial sums parked
// in `out` between chunks (same-thread global RMW), keeping live accs <= 44.

#define HW_ 9216            // 96*96 plane stride in floats
#define RS  68              // padded row stride for 64-ch chunk (floats)
#define S1F (96*RS)         // 6528
#define S2ROWS 136          // x in [-20,115] -> row = x+20
#define S2F (S2ROWS*RS)     // 9248
#define SMEM_BYTES ((S1F + S2F)*4)   // 63,104 B

__device__ __forceinline__ void stage_chunk(const float* __restrict__ in1,
                                            const float* __restrict__ in2,
                                            float* __restrict__ s1,
                                            float* __restrict__ s2,
                                            int b, int y, int y2, int cc, int tid)
{
    const float* g1 = in1 + ((size_t)(b * 128 + cc * 64) * 96 + y) * 96;
    #pragma unroll 1
    for (int i = tid; i < 96 * 16; i += 192) {
        int x = i % 96, g = i / 96;                 // g = float4 granule 0..15
        const float* p = g1 + g * 4 * HW_ + x;
        *(float4*)&s1[x * RS + g * 4] = make_float4(p[0], p[HW_], p[2*HW_], p[3*HW_]);
    }
    const float* g2 = in2 + ((size_t)(b * 128 + cc * 64) * 96 + y2) * 96;
    #pragma unroll 1
    for (int i = tid; i < 96 * 16; i += 192) {
        int x = i % 96, g = i / 96;
        const float* p = g2 + g * 4 * HW_ + x;
        *(float4*)&s2[(x + 20) * RS + g * 4] = make_float4(p[0], p[HW_], p[2*HW_], p[3*HW_]);
    }
}

// Accumulate the staged 64-ch chunk into acc[xi][jl], j = JLO+jl, for 4 output
// columns x0+2*xi. Lane owns granules cg and cg+8. bv row = x0 + 2*(JLO+u),
// u = jl + xi in [0, NJ+3).
template<int NJ>
__device__ __forceinline__ void accum4(const float* __restrict__ s1,
                                       const float* __restrict__ s2,
                                       int x0, int cg, int JLO, float (&acc)[4][NJ])
{
    #pragma unroll
    for (int k = 0; k < 2; k++) {
        const int cb = cg + 8 * k;
        const float* p1 = s1 + x0 * RS + cb * 4;
        const float4 a0 = *(const float4*)(p1);
        const float4 a1 = *(const float4*)(p1 + 2 * RS);
        const float4 a2 = *(const float4*)(p1 + 4 * RS);
        const float4 a3 = *(const float4*)(p1 + 6 * RS);
        const float* p2 = s2 + (x0 + 2 * JLO) * RS + cb * 4;
        #pragma unroll
        for (int u = 0; u < NJ + 3; u++) {
            const float4 bv = *(const float4*)(p2 + 2 * u * RS);
            if (u < NJ) {
                float v = acc[0][u];
                v = fmaf(a0.x, bv.x, v); v = fmaf(a0.y, bv.y, v);
                v = fmaf(a0.z, bv.z, v); v = fmaf(a0.w, bv.w, v);
                acc[0][u] = v;
            }
            if (u >= 1 && u - 1 < NJ) {
                float v = acc[1][u - 1];
                v = fmaf(a1.x, bv.x, v); v = fmaf(a1.y, bv.y, v);
                v = fmaf(a1.z, bv.z, v); v = fmaf(a1.w, bv.w, v);
                acc[1][u - 1] = v;
            }
            if (u >= 2 && u - 2 < NJ) {
                float v = acc[2][u - 2];
                v = fmaf(a2.x, bv.x, v); v = fmaf(a2.y, bv.y, v);
                v = fmaf(a2.z, bv.z, v); v = fmaf(a2.w, bv.w, v);
                acc[2][u - 2] = v;
            }
            if (u >= 3 && u - 3 < NJ) {
                float v = acc[3][u - 3];
                v = fmaf(a3.x, bv.x, v); v = fmaf(a3.y, bv.y, v);
                v = fmaf(a3.z, bv.z, v); v = fmaf(a3.w, bv.w, v);
                acc[3][u - 3] = v;
            }
        }
    }
}

// Butterfly-reduce across the 8 cg lanes; lane cg handles xi=cg&3, j parity cg>>2.
// FINAL=0: store raw partial. FINAL=1: add previously stored partial, scale, store.
template<int NJ, int FINAL>
__device__ __forceinline__ void reduce_store(float (&acc)[4][NJ], int JLO, int x0,
                                             int cg, float* __restrict__ out,
                                             size_t obase)
{
    #pragma unroll
    for (int xi = 0; xi < 4; xi++)
        #pragma unroll
        for (int j = 0; j < NJ; j++) {
            float v = acc[xi][j];
            v += __shfl_xor_sync(0xffffffffu, v, 1);
            v += __shfl_xor_sync(0xffffffffu, v, 2);
            v += __shfl_xor_sync(0xffffffffu, v, 4);
            acc[xi][j] = v;
        }
    const float inv  = 1.0f / 128.0f;
    const int   myxi = cg & 3;
    const int   par  = cg >> 2;
    float* o = out + obase + x0 + 2 * myxi;
    #pragma unroll
    for (int j = 0; j < NJ; j++) {
        if (((JLO + j) & 1) == par) {
            float* p = o + (size_t)(JLO + j) * HW_;
            if (FINAL)
                *p = (*p + acc[myxi][j]) * inv;
            else
                *p = acc[myxi][j];
        }
    }
}

__global__ __launch_bounds__(192, 3)
void corr_kernel(const float* __restrict__ in1, const float* __restrict__ in2,
                 float* __restrict__ out)
{
    extern __shared__ float smem[];
    float* s1 = smem;
    float* s2 = smem + S1F;

    const int tid   = threadIdx.x;
    const int y     = blockIdx.x;    // 0..95
    const int dyIdx = blockIdx.y;    // 0..20
    const int b     = blockIdx.z;    // 0..3

    const int y2 = y + (dyIdx - 10) * 2;
    const size_t obase = ((size_t)(b * 441 + dyIdx * 21) * 96 + y) * 96;

    if ((unsigned)y2 >= 96u) {
        // whole dy slab for this row is zeros
        for (int i = tid; i < 21 * 96; i += 192) {
            int j = i / 96, x = i - j * 96;
            out[obase + (size_t)j * HW_ + x] = 0.f;
        }
        return;
    }

    // zero halo rows of s2 once (x in [-20,-1] and [96,115]); never overwritten
    for (int i = tid; i < 40 * 16; i += 192) {
        int r = i % 40, g = i / 40;
        int row = (r < 20) ? r : (96 + r);        // rows 0..19, 116..135
        *(float4*)&s2[row * RS + g * 4] = make_float4(0.f, 0.f, 0.f, 0.f);
    }

    const int cg = tid & 7;                  // channel granule lane
    const int xs = tid >> 3;                 // 0..23
    const int x0 = 8 * (xs >> 1) + (xs & 1); // outputs x0+2*xi, xi=0..3, tile 0..95

    // ---- chunk 0: compute both j-halves, park raw partials in out ----
    stage_chunk(in1, in2, s1, s2, b, y, y2, 0, tid);
    __syncthreads();
    {
        float acc[4][11];
        #pragma unroll
        for (int xi = 0; xi < 4; xi++)
            #pragma unroll
            for (int j = 0; j < 11; j++) acc[xi][j] = 0.f;
        accum4<11>(s1, s2, x0, cg, 0, acc);
        reduce_store<11, 0>(acc, 0, x0, cg, out, obase);
    }
    {
        float acc[4][10];
        #pragma unroll
        for (int xi = 0; xi < 4; xi++)
            #pragma unroll
            for (int j = 0; j < 10; j++) acc[xi][j] = 0.f;
        accum4<10>(s1, s2, x0, cg, 11, acc);
        reduce_store<10, 0>(acc, 11, x0, cg, out, obase);
    }
    __syncthreads();

    // ---- chunk 1: accumulate, combine with parked partials, finalize ----
    stage_chunk(in1, in2, s1, s2, b, y, y2, 1, tid);
    __syncthreads();
    {
        float acc[4][11];
        #pragma unroll
        for (int xi = 0; xi < 4; xi++)
            #pragma unroll
            for (int j = 0; j < 11; j++) acc[xi][j] = 0.f;
        accum4<11>(s1, s2, x0, cg, 0, acc);
        reduce_store<11, 1>(acc, 0, x0, cg, out, obase);
    }
    {
        float acc[4][10];
        #pragma unroll
        for (int xi = 0; xi < 4; xi++)
            #pragma unroll
            for (int j = 0; j < 10; j++) acc[xi][j] = 0.f;
        accum4<10>(s1, s2, x0, cg, 11, acc);
        reduce_store<10, 1>(acc, 11, x0, cg, out, obase);
    }
}

extern "C" void kernel_launch(void* const* d_in, const int* in_sizes, int n_in,
                              void* d_out, int out_size)
{
    const float* in1 = (const float*)d_in[0];
    const float* in2 = (const float*)d_in[1];
    float* out = (float*)d_out;

    cudaFuncSetAttribute(corr_kernel, cudaFuncAttributeMaxDynamicSharedMemorySize, SMEM_BYTES);

    dim3 grid(96, 21, 4);   // y, dy, batch
    corr_kernel<<<grid, 192, SMEM_BYTES>>>(in1, in2, out);
}

// round 14
// speedup vs baseline: 2.3546x; 2.3546x over previous
#include <cuda_runtime.h>
#include <cstdint>

// FlowNetC correlation via tf32 mma.sync band-GEMM with parity packing.
// out[b, dy*21+j, y, x] = (1/128) sum_c in1[b,c,y,x] * in2[b,c,y2,x+2j-20], y2=y+2(dy-10)
// Parity p = x&1, u = x>>1 (48 rows/parity). B packed rows w = u' + 10,
// u' = (x2-p)/2; out(j,x): j = w - u (dense diagonals). Stored rows wS = w-8
// (56 rows; wS 0,1 and 50..55 are zero halo).
// Per warp (p, m0): A frags (16 ksteps x 4 regs, tf32) held in registers across
// all dy; per dy, 4-5 n-tiles of m16n8k8 mma over K=128.

#define HW_  9216
#define RSW  132             // tile row stride (32-bit words); 132 % 32 = 4 -> conflict-free frags
#define BROWS 56
#define BP0  0
#define BP1  (BROWS*RSW + 16)          // +16 words: keeps dual-parity STS.128 phases conflict-free
#define PADOFF (BP1 + BROWS*RSW)       // 14800
#define PSTR 98
#define SMEM_WORDS (PADOFF + 21*PSTR)  // 16858
#define SMEM_BYTES (SMEM_WORDS*4)      // 67432 -> 3 CTAs/SM

static __device__ __forceinline__ uint32_t f2tf(float f) {
    uint32_t r;
    asm("cvt.rna.tf32.f32 %0, %1;" : "=r"(r) : "f"(f));
    return r;
}

static __device__ __forceinline__ void mma_tf32(float (&d)[4], const uint32_t (&a)[4],
                                                uint32_t b0, uint32_t b1) {
    asm volatile(
        "mma.sync.aligned.m16n8k8.row.col.f32.tf32.tf32.f32 "
        "{%0,%1,%2,%3}, {%4,%5,%6,%7}, {%8,%9}, {%0,%1,%2,%3};"
        : "+f"(d[0]), "+f"(d[1]), "+f"(d[2]), "+f"(d[3])
        : "r"(a[0]), "r"(a[1]), "r"(a[2]), "r"(a[3]), "r"(b0), "r"(b1));
}

// Stage one image row (128 ch x 96 x, fp32) into the two parity tiles as tf32.
// Element (c, x) -> tile[p = x&1] row (rowoff + (x>>1)), word col c.
static __device__ __forceinline__ void stage_row(const float* __restrict__ g,
                                                 uint32_t* __restrict__ sm,
                                                 int rowoff, int tid)
{
    #pragma unroll 1
    for (int i = tid; i < 48 * 32; i += 192) {
        const int xp = i % 48, cp = i / 48;
        const float* pgl = g + (size_t)(4 * cp) * HW_ + 2 * xp;
        const float2 v0 = *(const float2*)(pgl);
        const float2 v1 = *(const float2*)(pgl + HW_);
        const float2 v2 = *(const float2*)(pgl + 2 * (size_t)HW_);
        const float2 v3 = *(const float2*)(pgl + 3 * (size_t)HW_);
        const uint4 ev = make_uint4(f2tf(v0.x), f2tf(v1.x), f2tf(v2.x), f2tf(v3.x));
        const uint4 od = make_uint4(f2tf(v0.y), f2tf(v1.y), f2tf(v2.y), f2tf(v3.y));
        const int r = (rowoff + xp) * RSW + 4 * cp;
        *(uint4*)(sm + BP0 + r) = ev;
        *(uint4*)(sm + BP1 + r) = od;
    }
}

__global__ void __launch_bounds__(192, 3)
corr_mma_kernel(const float* __restrict__ in1, const float* __restrict__ in2,
                float* __restrict__ out)
{
    extern __shared__ uint32_t sm[];
    const int tid  = threadIdx.x;
    const int warp = tid >> 5, lane = tid & 31;
    const int g8   = lane >> 2, tig = lane & 3;      // mma groupID / threadID-in-group
    const int y = blockIdx.x, b = blockIdx.y;

    const int p  = warp & 1;          // parity
    const int mi = warp >> 1;         // m-tile index 0..2
    const int m0 = 16 * mi;
    const int sLo = (mi == 0) ? 1 : 0;
    const int sHi = (mi == 2) ? 3 : 4;

    // ---- stage A (in1 row y) into B buffers (scratch), rows u = 0..47 ----
    stage_row(in1 + (size_t)b * 128 * HW_ + (size_t)y * 96, sm, 0, tid);
    __syncthreads();

    // ---- load A fragments for all 16 k-steps into registers ----
    uint32_t areg[16][4];
    {
        const uint32_t* ap = sm + (p ? BP1 : BP0);
        const int r0 = (m0 + g8) * RSW, r1 = (m0 + g8 + 8) * RSW;
        #pragma unroll
        for (int ks = 0; ks < 16; ks++) {
            const int c = 8 * ks + tig;
            areg[ks][0] = ap[r0 + c];
            areg[ks][1] = ap[r1 + c];
            areg[ks][2] = ap[r0 + c + 4];
            areg[ks][3] = ap[r1 + c + 4];
        }
    }
    __syncthreads();

    // ---- zero halo rows wS in {0,1} u [50,56) for both parities ----
    for (int i = tid; i < 8 * RSW; i += 192) {
        const int r = i / RSW, c = i - r * RSW;
        const int wS = (r < 2) ? r : (48 + r);
        sm[BP0 + wS * RSW + c] = 0u;
        sm[BP1 + wS * RSW + c] = 0u;
    }

    float* pad = (float*)(sm + PADOFF);
    const float inv = 1.0f / 128.0f;

    #pragma unroll 1
    for (int dy = 0; dy < 21; dy++) {
        const int y2 = y + 2 * (dy - 10);
        const bool valid = ((unsigned)y2 < 96u);

        if (valid)
            stage_row(in2 + (size_t)b * 128 * HW_ + (size_t)y2 * 96, sm, 2, tid);
        __syncthreads();

        if (valid) {
            float acc[5][4];
            #pragma unroll
            for (int s = 0; s < 5; s++)
                #pragma unroll
                for (int q = 0; q < 4; q++) acc[s][q] = 0.f;

            const uint32_t* bp = sm + (p ? BP1 : BP0);
            #pragma unroll
            for (int ks = 0; ks < 16; ks++) {
                #pragma unroll
                for (int s = 0; s < 5; s++) {
                    if (s < sLo || s > sHi) continue;
                    const int row = (m0 + 8 * s - 8 + g8) * RSW + 8 * ks + tig;
                    mma_tf32(acc[s], areg[ks], bp[row], bp[row + 4]);
                }
            }

            // scatter D frags into pad[j][x]
            const int x  = 2 * (m0 + g8) + p;
            #pragma unroll
            for (int s = 0; s < 5; s++) {
                if (s < sLo || s > sHi) continue;
                const int j0 = 8 * s + 2 * tig - g8;       // w0 + 2tig - u_lo
                if (j0 >= 0     && j0 < 21)     pad[j0 * PSTR + x]           = acc[s][0];
                if (j0 + 1 >= 0 && j0 + 1 < 21) pad[(j0 + 1) * PSTR + x]     = acc[s][1];
                const int j2 = j0 - 8;
                if (j2 >= 0     && j2 < 21)     pad[j2 * PSTR + x + 16]      = acc[s][2];
                if (j2 + 1 >= 0 && j2 + 1 < 21) pad[(j2 + 1) * PSTR + x + 16] = acc[s][3];
            }
        }
        __syncthreads();

        // masked coalesced copy (also emits zeros for invalid dy / out-of-window x2)
        const size_t obase = ((size_t)(b * 441 + dy * 21) * 96 + y) * 96;
        #pragma unroll 1
        for (int i = tid; i < 21 * 96; i += 192) {
            const int j = i / 96, x = i - 96 * j;
            const int x2 = x + 2 * j - 20;
            float v = 0.f;
            if (valid && (unsigned)x2 < 96u)
                v = pad[j * PSTR + x] * inv;
            out[obase + (size_t)j * HW_ + x] = v;
        }
    }
}

extern "C" void kernel_launch(void* const* d_in, const int* in_sizes, int n_in,
                              void* d_out, int out_size)
{
    const float* in1 = (const float*)d_in[0];
    const float* in2 = (const float*)d_in[1];
    float* out = (float*)d_out;

    cudaFuncSetAttribute(corr_mma_kernel, cudaFuncAttributeMaxDynamicSharedMemorySize, SMEM_BYTES);

    dim3 grid(96, 4);   // y, batch
    corr_mma_kernel<<<grid, 192, SMEM_BYTES>>>(in1, in2, out);
}